// round 14
// baseline (speedup 1.0000x reference)
#include <cuda_runtime.h>
#include <math.h>

// Problem constants (fixed by setup_inputs)
#define BATCH  16
#define DMODEL 4096
#define NKV    8
#define NHEADS 32
#define HD     128
#define NQKV   6144            // 4096 q + 1024 k + 1024 v
#define KSPLIT 64
#define KCHUNK 64              // 4096 / KSPLIT
#define ASPLIT 32              // attention KV splits
#define MAXK_LOC 72            // >= ceil(2049/32)=65, padded
#define SXLD   20              // smem x row stride (floats)
#define KROW4  (NKV * HD / 4)  // float4 stride between consecutive keys = 256
#define KROW2  (NKV * HD / 2)  // float2 stride between consecutive keys = 512

// ---------------- scratch (device globals; no allocation allowed) ----------------
__device__ __align__(16) float g_part1[KSPLIT * BATCH * NQKV];    // qkv split-K partials
__device__ __align__(16) float g_part2[KSPLIT * BATCH * DMODEL];  // wo  split-K partials
__device__ __align__(16) float g_q   [BATCH * NHEADS * HD];
__device__ __align__(16) float g_knew[BATCH * NKV * HD];
__device__ __align__(16) float g_vnew[BATCH * NKV * HD];
__device__ __align__(16) float g_attn[BATCH * DMODEL];
// attention split-KV partials: g_pO [blk][h][HD], g_pm/g_ps [bk][h][split]
__device__ __align__(16) float g_pO[BATCH * NKV * ASPLIT * 4 * HD];
__device__ __align__(16) float g_pm[BATCH * NKV * 4 * ASPLIT];
__device__ __align__(16) float g_ps[BATCH * NKV * 4 * ASPLIT];

// ---------------- packed f32x2 helpers (sm_103a) ----------------
__device__ __forceinline__ unsigned long long pack2(float f) {
    unsigned long long r;
    unsigned int u = __float_as_uint(f);
    asm("mov.b64 %0, {%1, %1};" : "=l"(r) : "r"(u));
    return r;
}
__device__ __forceinline__ void fma2(unsigned long long& acc,
                                     unsigned long long a, unsigned long long b) {
    asm("fma.rn.f32x2 %0, %1, %2, %0;" : "+l"(acc) : "l"(a), "l"(b));
}
__device__ __forceinline__ void unpack2(unsigned long long v, float& lo, float& hi) {
    unsigned int a, b;
    asm("mov.b64 {%0, %1}, %2;" : "=r"(a), "=r"(b) : "l"(v));
    lo = __uint_as_float(a); hi = __uint_as_float(b);
}

union F4U { float4 f; unsigned long long u[2]; };

// compute one 8-k batch of the GEMM inner loop
__device__ __forceinline__ void gemm_compute8(
    const float2 (&wv)[8], const float* sxk,
    unsigned long long (&accx)[8], unsigned long long (&accy)[8])
{
    #pragma unroll
    for (int u = 0; u < 8; u++) {
        unsigned long long wxx = pack2(wv[u].x);
        unsigned long long wyy = pack2(wv[u].y);
        const float4* row = (const float4*)(sxk + u * SXLD);
        #pragma unroll
        for (int p = 0; p < 4; p++) {
            F4U t; t.f = row[p];                 // broadcast LDS.128
            fma2(accx[2*p],     t.u[0], wxx);
            fma2(accx[2*p + 1], t.u[1], wxx);
            fma2(accy[2*p],     t.u[0], wyy);
            fma2(accy[2*p + 1], t.u[1], wyy);
        }
    }
}

// ---------------------------------------------------------------------------------
// Skinny GEMM: Y[16, ntot] = X[16, 4096] @ W[4096, ntot], split-K partials.
// Packed f32x2 accumulation, double-buffered weight batches (software pipeline).
// Grid: (ntot/512, KSPLIT), 256 threads.
// ---------------------------------------------------------------------------------
__global__ void __launch_bounds__(256) gemm16_part(
    const float* __restrict__ x_ext,
    const float* __restrict__ wa, const float* __restrict__ wb,
    const float* __restrict__ wc,
    int lda, int ldb, int ldc, int r1, int r2, int ntot, int sel)
{
    __shared__ __align__(16) float sx[KCHUNK * SXLD];

    const float* __restrict__ x = sel ? g_attn : x_ext;
    float* __restrict__ part    = sel ? g_part2 : g_part1;

    const int tid   = threadIdx.x;
    const int kbase = blockIdx.y * KCHUNK;

    // stage x tile transposed: sx[k][m] = x[m][kbase+k]
    #pragma unroll
    for (int i = 0; i < (16 * KCHUNK) / 256; i++) {
        int e = tid + i * 256;
        int m = e >> 6;               // 0..15
        int k = e & 63;               // 0..63
        sx[k * SXLD + m] = x[m * DMODEL + kbase + k];
    }
    __syncthreads();

    const int base = blockIdx.x * 512;
    const float* w; int ld, lc;
    if (base < r1)      { w = wa; ld = lda; lc = base; }
    else if (base < r2) { w = wb; ld = ldb; lc = base - r1; }
    else                { w = wc; ld = ldc; lc = base - r2; }

    const float2* __restrict__ wp =
        (const float2*)(w + (size_t)kbase * ld + lc) + tid;
    const int ld2 = ld >> 1;

    unsigned long long accx[8], accy[8];
    #pragma unroll
    for (int mp = 0; mp < 8; mp++) { accx[mp] = 0ull; accy[mp] = 0ull; }

    float2 wva[8], wvb[8];
    #pragma unroll
    for (int u = 0; u < 8; u++) wva[u] = wp[(size_t)u * ld2];

    #pragma unroll
    for (int k0 = 0; k0 < KCHUNK; k0 += 16) {
        // prefetch batch k0+8 while computing batch k0
        #pragma unroll
        for (int u = 0; u < 8; u++) wvb[u] = wp[(size_t)(k0 + 8 + u) * ld2];
        gemm_compute8(wva, &sx[k0 * SXLD], accx, accy);

        // prefetch batch k0+16 (if any) while computing batch k0+8
        if (k0 + 16 < KCHUNK) {
            #pragma unroll
            for (int u = 0; u < 8; u++) wva[u] = wp[(size_t)(k0 + 16 + u) * ld2];
        }
        gemm_compute8(wvb, &sx[(k0 + 8) * SXLD], accx, accy);
    }

    // epilogue: unpack m-pairs, store float2 per m
    float2* pp = (float2*)(part + (size_t)(blockIdx.y * 16) * ntot + base) + tid;
    const int step = ntot >> 1;
    #pragma unroll
    for (int mp = 0; mp < 8; mp++) {
        float ax0, ax1, ay0, ay1;
        unpack2(accx[mp], ax0, ax1);
        unpack2(accy[mp], ay0, ay1);
        float2 o0; o0.x = ax0; o0.y = ay0;
        float2 o1; o1.x = ax1; o1.y = ay1;
        pp[(size_t)(2*mp)     * step] = o0;
        pp[(size_t)(2*mp + 1) * step] = o1;
    }
}

// ---------------------------------------------------------------------------------
// Reduce QKV split-K partials + apply RoPE; scatter to g_q / g_knew / g_vnew.
// ---------------------------------------------------------------------------------
__global__ void __launch_bounds__(256) rope_reduce(
    const float* __restrict__ fcos, const float* __restrict__ fsin)
{
    int idx = blockIdx.x * 256 + threadIdx.x;    // 0 .. 16*3072-1
    int b = idx / 3072;
    int p = idx - b * 3072;                       // pair index within row
    int n0 = 2 * p;                               // 0..6142 even

    const float2* __restrict__ src = (const float2*)g_part1;
    float v0 = 0.f, v1 = 0.f;
    #pragma unroll
    for (int s = 0; s < KSPLIT; s++) {
        float2 t = src[(size_t)(s * 16 + b) * (NQKV / 2) + p];
        v0 += t.x; v1 += t.y;
    }

    if (n0 < 4096) {                              // Q
        int i = (n0 & (HD - 1)) >> 1;
        float c = fcos[i], s = fsin[i];
        float2 o; o.x = v0 * c - v1 * s; o.y = v0 * s + v1 * c;
        *(float2*)&g_q[(size_t)b * 4096 + n0] = o;
    } else if (n0 < 5120) {                       // K (rope)
        int nl = n0 - 4096;
        int i = (nl & (HD - 1)) >> 1;
        float c = fcos[i], s = fsin[i];
        float2 o; o.x = v0 * c - v1 * s; o.y = v0 * s + v1 * c;
        *(float2*)&g_knew[(size_t)b * 1024 + nl] = o;
    } else {                                      // V (copy)
        int nl = n0 - 5120;
        float2 o; o.x = v0; o.y = v1;
        *(float2*)&g_vnew[(size_t)b * 1024 + nl] = o;
    }
}

// ---------------- QK dot for one key across 4 rep heads ----------------
__device__ __forceinline__ void qk_dot4(const float4 (&k4)[4],
                                        const float4 (&qreg)[4][4],
                                        float (&acc)[4])
{
    #pragma unroll
    for (int h = 0; h < 4; h++) {
        float a = 0.f;
        #pragma unroll
        for (int i = 0; i < 4; i++) {
            a = fmaf(k4[i].x, qreg[h][i].x, a);
            a = fmaf(k4[i].y, qreg[h][i].y, a);
            a = fmaf(k4[i].z, qreg[h][i].z, a);
            a = fmaf(k4[i].w, qreg[h][i].w, a);
        }
        acc[h] = a;
    }
    #pragma unroll
    for (int off = 1; off <= 4; off <<= 1) {
        #pragma unroll
        for (int h = 0; h < 4; h++)
            acc[h] += __shfl_xor_sync(0xffffffffu, acc[h], off);
    }
}

// ---------------------------------------------------------------------------------
// Attention partial (split-KV). Grid: BATCH*NKV*ASPLIT = 4096 blocks, 256 thr.
// Phase 1 region-split; phase 3: 4 key-quarters x 64 float2 d-lanes.
// ---------------------------------------------------------------------------------
__global__ void __launch_bounds__(256) attn_part(
    const float* __restrict__ cache_k, const float* __restrict__ cache_v,
    const float* __restrict__ sh_k,    const float* __restrict__ sh_v,
    const int* __restrict__ p_sp,      const int* __restrict__ p_spl)
{
    __shared__ __align__(16) float sc[4][MAXK_LOC];
    __shared__ float ssum[4], smax[4];
    __shared__ __align__(16) float sacc[4][4][HD];

    const int blk  = blockIdx.x;
    const int sp_i = blk & (ASPLIT - 1);
    const int bk   = blk / ASPLIT;                // b*8 + kvh
    const int kvh  = bk & 7;
    const int b    = bk >> 3;

    const int sp  = *p_sp;
    const int spl = *p_spl;
    const int nk  = sp + 1;                       // 2049
    const int klen = (nk + ASPLIT - 1) / ASPLIT;  // 65
    const int j0  = sp_i * klen;
    const int j1  = min(nk, j0 + klen);
    const int ln  = j1 - j0;

    const int tid  = threadIdx.x;
    const int wid  = tid >> 5;
    const int lane = tid & 31;
    const int sub  = lane & 7;
    const int grp  = lane >> 3;
    const int gid  = wid * 4 + grp;               // 8-lane group id, 0..31

    // q for the 4 rep heads of this kv head
    float4 qreg[4][4];
    const float4* qb = (const float4*)(g_q + (size_t)b * DMODEL + (size_t)(kvh * 4) * HD);
    #pragma unroll
    for (int h = 0; h < 4; h++)
        #pragma unroll
        for (int i = 0; i < 4; i++)
            qreg[h][i] = qb[h * 32 + sub + 8 * i];

    const float scale = rsqrtf((float)HD);

    // ---- phase 1: scores, region-split ----
    // segment A: shared prefix keys [j0, min(j1, spl))
    {
        int sa = j0, sb = min(j1, spl);
        if (sa < sb) {
            const float4* base4 = (const float4*)(sh_k + ((size_t)sa * NKV + kvh) * HD);
            int trips = (sb - sa - 4 * wid + 31) >> 5;   // warp-uniform
            int j = sa + gid;
            #pragma unroll 2
            for (int t = 0; t < trips; t++, j += 32) {
                int row = (j < sb ? j : sa) - sa;
                const float4* kp4 = base4 + (size_t)row * KROW4;
                float4 k4[4];
                #pragma unroll
                for (int i = 0; i < 4; i++) k4[i] = kp4[sub + 8 * i];
                float acc[4];
                qk_dot4(k4, qreg, acc);
                if (sub < 4 && j < sb) sc[sub][j - j0] = acc[sub] * scale;
            }
        }
    }
    // segment B: batch cache keys [max(j0,spl), min(j1, nk-1))
    {
        int sa = max(j0, spl), sb = min(j1, nk - 1);
        if (sa < sb) {
            const float4* base4 = (const float4*)
                (cache_k + (((size_t)b * 4096 + (sa - spl)) * NKV + kvh) * HD);
            int trips = (sb - sa - 4 * wid + 31) >> 5;   // warp-uniform
            int j = sa + gid;
            #pragma unroll 2
            for (int t = 0; t < trips; t++, j += 32) {
                int row = (j < sb ? j : sa) - sa;
                const float4* kp4 = base4 + (size_t)row * KROW4;
                float4 k4[4];
                #pragma unroll
                for (int i = 0; i < 4; i++) k4[i] = kp4[sub + 8 * i];
                float acc[4];
                qk_dot4(k4, qreg, acc);
                if (sub < 4 && j < sb) sc[sub][j - j0] = acc[sub] * scale;
            }
        }
    }
    // segment C: the new key (only in the last split); warp 0 handles it
    if (j1 == nk && wid == 0) {
        const float4* kp4 = (const float4*)(g_knew + ((size_t)b * NKV + kvh) * HD);
        float4 k4[4];
        #pragma unroll
        for (int i = 0; i < 4; i++) k4[i] = kp4[sub + 8 * i];
        float acc[4];
        qk_dot4(k4, qreg, acc);
        if (sub < 4 && grp == 0) sc[sub][nk - 1 - j0] = acc[sub] * scale;
    }
    __syncthreads();

    // ---- phase 2: local softmax stats ----
    if (wid < 4) {
        const int h = wid;
        float m = -1e30f;
        for (int jl = lane; jl < ln; jl += 32) m = fmaxf(m, sc[h][jl]);
        #pragma unroll
        for (int off = 16; off >= 1; off >>= 1)
            m = fmaxf(m, __shfl_xor_sync(0xffffffffu, m, off));
        float s = 0.f;
        for (int jl = lane; jl < ln; jl += 32) {
            float e = __expf(sc[h][jl] - m);
            sc[h][jl] = e;
            s += e;
        }
        #pragma unroll
        for (int off = 16; off >= 1; off >>= 1)
            s += __shfl_xor_sync(0xffffffffu, s, off);
        if (lane == 0) { ssum[h] = s; smax[h] = m; }
    }
    __syncthreads();

    // ---- phase 3: partial O, 4 key-quarters x 64 float2 lanes ----
    const int qtr = tid >> 6;                    // 0..3: quarter of key range
    const int dp  = tid & 63;                    // float2 index within head dim
    const int La  = j0 + ((ln * qtr) >> 2);      // global j range [La, Lb)
    const int Lb  = j0 + ((ln * (qtr + 1)) >> 2);

    float2 a[4];
    #pragma unroll
    for (int h = 0; h < 4; h++) { a[h].x = 0.f; a[h].y = 0.f; }

    // segment A: shared prefix
    {
        int sa = La, sb = min(Lb, spl);
        if (sa < sb) {
            const float2* p = (const float2*)(sh_v + ((size_t)sa * NKV + kvh) * HD) + dp;
            int jl = sa - j0;
            #pragma unroll 4
            for (int j = sa; j < sb; j++) {
                float2 v = *p; p += KROW2;
                #pragma unroll
                for (int h = 0; h < 4; h++) {
                    float w = sc[h][jl];
                    a[h].x = fmaf(w, v.x, a[h].x);
                    a[h].y = fmaf(w, v.y, a[h].y);
                }
                jl++;
            }
        }
    }
    // segment B: batch cache
    {
        int sa = max(La, spl), sb = min(Lb, nk - 1);
        if (sa < sb) {
            const float2* p = (const float2*)
                (cache_v + (((size_t)b * 4096 + (sa - spl)) * NKV + kvh) * HD) + dp;
            int jl = sa - j0;
            #pragma unroll 4
            for (int j = sa; j < sb; j++) {
                float2 v = *p; p += KROW2;
                #pragma unroll
                for (int h = 0; h < 4; h++) {
                    float w = sc[h][jl];
                    a[h].x = fmaf(w, v.x, a[h].x);
                    a[h].y = fmaf(w, v.y, a[h].y);
                }
                jl++;
            }
        }
    }
    // segment C: the new key (only the quarter whose range ends at nk)
    if (Lb == nk) {
        float2 v = ((const float2*)(g_vnew + ((size_t)b * NKV + kvh) * HD))[dp];
        int jl = (nk - 1) - j0;
        #pragma unroll
        for (int h = 0; h < 4; h++) {
            float w = sc[h][jl];
            a[h].x = fmaf(w, v.x, a[h].x);
            a[h].y = fmaf(w, v.y, a[h].y);
        }
    }

    #pragma unroll
    for (int h = 0; h < 4; h++)
        *(float2*)&sacc[qtr][h][2 * dp] = a[h];
    __syncthreads();

    if (tid < HD) {
        #pragma unroll
        for (int h = 0; h < 4; h++)
            g_pO[((size_t)blk * 4 + h) * HD + tid] =
                sacc[0][h][tid] + sacc[1][h][tid] + sacc[2][h][tid] + sacc[3][h][tid];
    }
    if (tid < 4) {
        g_pm[((size_t)bk * 4 + tid) * ASPLIT + sp_i] = smax[tid];
        g_ps[((size_t)bk * 4 + tid) * ASPLIT + sp_i] = ssum[tid];
    }
}

// ---------------------------------------------------------------------------------
// Combine attention splits. Grid: BATCH*NKV*4 = 512 blocks, 128 threads.
// One block per (bk, h); thread = d.
// ---------------------------------------------------------------------------------
__global__ void __launch_bounds__(128) attn_combine()
{
    const int blkid = blockIdx.x;    // bk*4 + h
    const int bk  = blkid >> 2;
    const int h   = blkid & 3;
    const int d   = threadIdx.x;
    const int b   = bk >> 3;
    const int kvh = bk & 7;

    const float4* pm4 = (const float4*)&g_pm[((size_t)bk * 4 + h) * ASPLIT];
    const float4* ps4 = (const float4*)&g_ps[((size_t)bk * 4 + h) * ASPLIT];

    float m[ASPLIT], s[ASPLIT];
    #pragma unroll
    for (int q = 0; q < ASPLIT / 4; q++) {
        float4 t = pm4[q];
        m[4*q] = t.x; m[4*q+1] = t.y; m[4*q+2] = t.z; m[4*q+3] = t.w;
        float4 u = ps4[q];
        s[4*q] = u.x; s[4*q+1] = u.y; s[4*q+2] = u.z; s[4*q+3] = u.w;
    }
    float mg = -1e30f;
    #pragma unroll
    for (int i = 0; i < ASPLIT; i++) mg = fmaxf(mg, m[i]);

    float num = 0.f, den = 0.f;
    #pragma unroll
    for (int i = 0; i < ASPLIT; i++) {
        float w = __expf(m[i] - mg);
        num = fmaf(w, g_pO[(((size_t)bk * ASPLIT + i) * 4 + h) * HD + d], num);
        den = fmaf(w, s[i], den);
    }
    g_attn[(size_t)b * DMODEL + (size_t)(kvh * 4 + h) * HD + d] = num / den;
}

// ---------------------------------------------------------------------------------
// Final reduce of WO split-K partials into d_out. 65536 elements.
// ---------------------------------------------------------------------------------
__global__ void __launch_bounds__(256) reduce_out(float* __restrict__ out)
{
    int idx = blockIdx.x * 256 + threadIdx.x;    // 0..65535
    int b = idx >> 12;
    int n = idx & 4095;
    float s = 0.f;
    #pragma unroll
    for (int sp = 0; sp < KSPLIT; sp++)
        s += g_part2[(size_t)(sp * 16 + b) * DMODEL + n];
    out[idx] = s;
}

// ---------------------------------------------------------------------------------
extern "C" void kernel_launch(void* const* d_in, const int* in_sizes, int n_in,
                              void* d_out, int out_size)
{
    const float* x        = (const float*)d_in[0];
    const float* wq       = (const float*)d_in[1];
    const float* wk       = (const float*)d_in[2];
    const float* wv       = (const float*)d_in[3];
    const float* wo       = (const float*)d_in[4];
    const float* cache_k  = (const float*)d_in[5];
    const float* cache_v  = (const float*)d_in[6];
    const float* sh_k     = (const float*)d_in[7];
    const float* sh_v     = (const float*)d_in[8];
    const float* fcos     = (const float*)d_in[9];
    const float* fsin     = (const float*)d_in[10];
    const int*   p_sp     = (const int*)d_in[11];
    const int*   p_spl    = (const int*)d_in[12];
    float*       out      = (float*)d_out;

    // 1) QKV projection split-K partials (768 blocks)
    dim3 g1(NQKV / 512, KSPLIT);
    gemm16_part<<<g1, 256>>>(x, wq, wk, wv,
                             4096, 1024, 1024, 4096, 5120, NQKV, 0);

    // 2) reduce + RoPE
    rope_reduce<<<(BATCH * 3072) / 256, 256>>>(fcos, fsin);

    // 3) attention split-KV partials (4096 blocks) + combine (512 blocks)
    attn_part<<<BATCH * NKV * ASPLIT, 256>>>(cache_k, cache_v, sh_k, sh_v, p_sp, p_spl);
    attn_combine<<<BATCH * NKV * 4, 128>>>();

    // 4) output projection split-K partials (512 blocks)
    dim3 g2(DMODEL / 512, KSPLIT);
    gemm16_part<<<g2, 256>>>(x, wo, wo, wo,
                             4096, 4096, 4096, 1 << 28, 1 << 29, DMODEL, 1);

    // 5) final reduce into d_out
    reduce_out<<<(BATCH * DMODEL) / 256, 256>>>(out);
}

// round 16
// speedup vs baseline: 1.0650x; 1.0650x over previous
#include <cuda_runtime.h>
#include <math.h>

// Problem constants (fixed by setup_inputs)
#define BATCH  16
#define DMODEL 4096
#define NKV    8
#define NHEADS 32
#define HD     128
#define NQKV   6144            // 4096 q + 1024 k + 1024 v
#define KSPLIT 64
#define KCHUNK 64              // 4096 / KSPLIT
#define ASPLIT 16              // attention KV splits (R10 measured optimum)
#define MAXK_LOC 136           // >= ceil(2049/16)=129, padded
#define SXLD   20              // smem x row stride (floats)
#define KROW4  (NKV * HD / 4)  // float4 stride between consecutive keys = 256

// ---------------- scratch (device globals; no allocation allowed) ----------------
__device__ __align__(16) float g_part1[KSPLIT * BATCH * NQKV];    // qkv split-K partials
__device__ __align__(16) float g_part2[KSPLIT * BATCH * DMODEL];  // wo  split-K partials
__device__ __align__(16) float g_q   [BATCH * NHEADS * HD];
__device__ __align__(16) float g_knew[BATCH * NKV * HD];
__device__ __align__(16) float g_vnew[BATCH * NKV * HD];
__device__ __align__(16) float g_attn[BATCH * DMODEL];
// attention split-KV partials: g_pO [blk][h][HD], g_pm/g_ps [bk][h][split]
__device__ __align__(16) float g_pO[BATCH * NKV * ASPLIT * 4 * HD];
__device__ __align__(16) float g_pm[BATCH * NKV * 4 * ASPLIT];
__device__ __align__(16) float g_ps[BATCH * NKV * 4 * ASPLIT];

// ---------------- packed f32x2 helpers (sm_103a) ----------------
__device__ __forceinline__ unsigned long long pack2(float f) {
    unsigned long long r;
    unsigned int u = __float_as_uint(f);
    asm("mov.b64 %0, {%1, %1};" : "=l"(r) : "r"(u));
    return r;
}
__device__ __forceinline__ void fma2(unsigned long long& acc,
                                     unsigned long long a, unsigned long long b) {
    asm("fma.rn.f32x2 %0, %1, %2, %0;" : "+l"(acc) : "l"(a), "l"(b));
}
__device__ __forceinline__ void unpack2(unsigned long long v, float& lo, float& hi) {
    unsigned int a, b;
    asm("mov.b64 {%0, %1}, %2;" : "=r"(a), "=r"(b) : "l"(v));
    lo = __uint_as_float(a); hi = __uint_as_float(b);
}

union F4U { float4 f; unsigned long long u[2]; };

// compute one 8-k batch of the GEMM inner loop
__device__ __forceinline__ void gemm_compute8(
    const float2 (&wv)[8], const float* sxk,
    unsigned long long (&accx)[8], unsigned long long (&accy)[8])
{
    #pragma unroll
    for (int u = 0; u < 8; u++) {
        unsigned long long wxx = pack2(wv[u].x);
        unsigned long long wyy = pack2(wv[u].y);
        const float4* row = (const float4*)(sxk + u * SXLD);
        #pragma unroll
        for (int p = 0; p < 4; p++) {
            F4U t; t.f = row[p];                 // broadcast LDS.128
            fma2(accx[2*p],     t.u[0], wxx);
            fma2(accx[2*p + 1], t.u[1], wxx);
            fma2(accy[2*p],     t.u[0], wyy);
            fma2(accy[2*p + 1], t.u[1], wyy);
        }
    }
}

// ---------------------------------------------------------------------------------
// Skinny GEMM: Y[16, ntot] = X[16, 4096] @ W[4096, ntot], split-K partials.
// Packed f32x2 accumulation, double-buffered weight batches (software pipeline).
// Grid: (ntot/512, KSPLIT), 256 threads.
// ---------------------------------------------------------------------------------
__global__ void __launch_bounds__(256) gemm16_part(
    const float* __restrict__ x_ext,
    const float* __restrict__ wa, const float* __restrict__ wb,
    const float* __restrict__ wc,
    int lda, int ldb, int ldc, int r1, int r2, int ntot, int sel)
{
    __shared__ __align__(16) float sx[KCHUNK * SXLD];

    const float* __restrict__ x = sel ? g_attn : x_ext;
    float* __restrict__ part    = sel ? g_part2 : g_part1;

    const int tid   = threadIdx.x;
    const int kbase = blockIdx.y * KCHUNK;

    // stage x tile transposed: sx[k][m] = x[m][kbase+k]
    #pragma unroll
    for (int i = 0; i < (16 * KCHUNK) / 256; i++) {
        int e = tid + i * 256;
        int m = e >> 6;               // 0..15
        int k = e & 63;               // 0..63
        sx[k * SXLD + m] = x[m * DMODEL + kbase + k];
    }
    __syncthreads();

    const int base = blockIdx.x * 512;
    const float* w; int ld, lc;
    if (base < r1)      { w = wa; ld = lda; lc = base; }
    else if (base < r2) { w = wb; ld = ldb; lc = base - r1; }
    else                { w = wc; ld = ldc; lc = base - r2; }

    const float2* __restrict__ wp =
        (const float2*)(w + (size_t)kbase * ld + lc) + tid;
    const int ld2 = ld >> 1;

    unsigned long long accx[8], accy[8];
    #pragma unroll
    for (int mp = 0; mp < 8; mp++) { accx[mp] = 0ull; accy[mp] = 0ull; }

    float2 wva[8], wvb[8];
    #pragma unroll
    for (int u = 0; u < 8; u++) wva[u] = wp[(size_t)u * ld2];

    #pragma unroll
    for (int k0 = 0; k0 < KCHUNK; k0 += 16) {
        // prefetch batch k0+8 while computing batch k0
        #pragma unroll
        for (int u = 0; u < 8; u++) wvb[u] = wp[(size_t)(k0 + 8 + u) * ld2];
        gemm_compute8(wva, &sx[k0 * SXLD], accx, accy);

        // prefetch batch k0+16 (if any) while computing batch k0+8
        if (k0 + 16 < KCHUNK) {
            #pragma unroll
            for (int u = 0; u < 8; u++) wva[u] = wp[(size_t)(k0 + 16 + u) * ld2];
        }
        gemm_compute8(wvb, &sx[(k0 + 8) * SXLD], accx, accy);
    }

    // epilogue: unpack m-pairs, store float2 per m
    float2* pp = (float2*)(part + (size_t)(blockIdx.y * 16) * ntot + base) + tid;
    const int step = ntot >> 1;
    #pragma unroll
    for (int mp = 0; mp < 8; mp++) {
        float ax0, ax1, ay0, ay1;
        unpack2(accx[mp], ax0, ax1);
        unpack2(accy[mp], ay0, ay1);
        float2 o0; o0.x = ax0; o0.y = ay0;
        float2 o1; o1.x = ax1; o1.y = ay1;
        pp[(size_t)(2*mp)     * step] = o0;
        pp[(size_t)(2*mp + 1) * step] = o1;
    }
}

// ---------------------------------------------------------------------------------
// Reduce QKV split-K partials + apply RoPE; scatter to g_q / g_knew / g_vnew.
// ---------------------------------------------------------------------------------
__global__ void __launch_bounds__(256) rope_reduce(
    const float* __restrict__ fcos, const float* __restrict__ fsin)
{
    int idx = blockIdx.x * 256 + threadIdx.x;    // 0 .. 16*3072-1
    int b = idx / 3072;
    int p = idx - b * 3072;                       // pair index within row
    int n0 = 2 * p;                               // 0..6142 even

    const float2* __restrict__ src = (const float2*)g_part1;
    float v0 = 0.f, v1 = 0.f;
    #pragma unroll
    for (int s = 0; s < KSPLIT; s++) {
        float2 t = src[(size_t)(s * 16 + b) * (NQKV / 2) + p];
        v0 += t.x; v1 += t.y;
    }

    if (n0 < 4096) {                              // Q
        int i = (n0 & (HD - 1)) >> 1;
        float c = fcos[i], s = fsin[i];
        float2 o; o.x = v0 * c - v1 * s; o.y = v0 * s + v1 * c;
        *(float2*)&g_q[(size_t)b * 4096 + n0] = o;
    } else if (n0 < 5120) {                       // K (rope)
        int nl = n0 - 4096;
        int i = (nl & (HD - 1)) >> 1;
        float c = fcos[i], s = fsin[i];
        float2 o; o.x = v0 * c - v1 * s; o.y = v0 * s + v1 * c;
        *(float2*)&g_knew[(size_t)b * 1024 + nl] = o;
    } else {                                      // V (copy)
        int nl = n0 - 5120;
        float2 o; o.x = v0; o.y = v1;
        *(float2*)&g_vnew[(size_t)b * 1024 + nl] = o;
    }
}

// ---------------- QK dot for one key across 4 rep heads ----------------
__device__ __forceinline__ void qk_dot4(const float4 (&k4)[4],
                                        const float4 (&qreg)[4][4],
                                        float (&acc)[4])
{
    #pragma unroll
    for (int h = 0; h < 4; h++) {
        float a = 0.f;
        #pragma unroll
        for (int i = 0; i < 4; i++) {
            a = fmaf(k4[i].x, qreg[h][i].x, a);
            a = fmaf(k4[i].y, qreg[h][i].y, a);
            a = fmaf(k4[i].z, qreg[h][i].z, a);
            a = fmaf(k4[i].w, qreg[h][i].w, a);
        }
        acc[h] = a;
    }
    #pragma unroll
    for (int off = 1; off <= 4; off <<= 1) {
        #pragma unroll
        for (int h = 0; h < 4; h++)
            acc[h] += __shfl_xor_sync(0xffffffffu, acc[h], off);
    }
}

// ---------------------------------------------------------------------------------
// Attention partial (split-KV). Grid: BATCH*NKV*ASPLIT = 2048 blocks, 256 thr.
// Exact R10 configuration (measured 172.5us overall).
// ---------------------------------------------------------------------------------
__global__ void __launch_bounds__(256) attn_part(
    const float* __restrict__ cache_k, const float* __restrict__ cache_v,
    const float* __restrict__ sh_k,    const float* __restrict__ sh_v,
    const int* __restrict__ p_sp,      const int* __restrict__ p_spl)
{
    __shared__ __align__(16) float sc[4][MAXK_LOC];
    __shared__ float ssum[4], smax[4];
    __shared__ __align__(16) float sacc[2][4][HD];

    const int blk  = blockIdx.x;
    const int sp_i = blk & (ASPLIT - 1);
    const int bk   = blk >> 4;                    // b*8 + kvh
    const int kvh  = bk & 7;
    const int b    = bk >> 3;

    const int sp  = *p_sp;
    const int spl = *p_spl;
    const int nk  = sp + 1;                       // 2049
    const int klen = (nk + ASPLIT - 1) / ASPLIT;  // 129
    const int j0  = sp_i * klen;
    const int j1  = min(nk, j0 + klen);
    const int ln  = j1 - j0;

    const int tid  = threadIdx.x;
    const int wid  = tid >> 5;
    const int lane = tid & 31;
    const int sub  = lane & 7;
    const int grp  = lane >> 3;
    const int gid  = wid * 4 + grp;               // 8-lane group id, 0..31

    // q for the 4 rep heads of this kv head
    float4 qreg[4][4];
    const float4* qb = (const float4*)(g_q + (size_t)b * DMODEL + (size_t)(kvh * 4) * HD);
    #pragma unroll
    for (int h = 0; h < 4; h++)
        #pragma unroll
        for (int i = 0; i < 4; i++)
            qreg[h][i] = qb[h * 32 + sub + 8 * i];

    const float scale = rsqrtf((float)HD);

    // ---- phase 1: scores, region-split ----
    // segment A: shared prefix keys [j0, min(j1, spl))
    {
        int sa = j0, sb = min(j1, spl);
        if (sa < sb) {
            const float4* base4 = (const float4*)(sh_k + ((size_t)sa * NKV + kvh) * HD);
            int trips = (sb - sa - 4 * wid + 31) >> 5;   // warp-uniform
            int j = sa + gid;
            #pragma unroll 2
            for (int t = 0; t < trips; t++, j += 32) {
                int row = (j < sb ? j : sa) - sa;
                const float4* kp4 = base4 + (size_t)row * KROW4;
                float4 k4[4];
                #pragma unroll
                for (int i = 0; i < 4; i++) k4[i] = kp4[sub + 8 * i];
                float acc[4];
                qk_dot4(k4, qreg, acc);
                if (sub < 4 && j < sb) sc[sub][j - j0] = acc[sub] * scale;
            }
        }
    }
    // segment B: batch cache keys [max(j0,spl), min(j1, nk-1))
    {
        int sa = max(j0, spl), sb = min(j1, nk - 1);
        if (sa < sb) {
            const float4* base4 = (const float4*)
                (cache_k + (((size_t)b * 4096 + (sa - spl)) * NKV + kvh) * HD);
            int trips = (sb - sa - 4 * wid + 31) >> 5;   // warp-uniform
            int j = sa + gid;
            #pragma unroll 2
            for (int t = 0; t < trips; t++, j += 32) {
                int row = (j < sb ? j : sa) - sa;
                const float4* kp4 = base4 + (size_t)row * KROW4;
                float4 k4[4];
                #pragma unroll
                for (int i = 0; i < 4; i++) k4[i] = kp4[sub + 8 * i];
                float acc[4];
                qk_dot4(k4, qreg, acc);
                if (sub < 4 && j < sb) sc[sub][j - j0] = acc[sub] * scale;
            }
        }
    }
    // segment C: the new key (only in the last split); warp 0 handles it
    if (j1 == nk && wid == 0) {
        const float4* kp4 = (const float4*)(g_knew + ((size_t)b * NKV + kvh) * HD);
        float4 k4[4];
        #pragma unroll
        for (int i = 0; i < 4; i++) k4[i] = kp4[sub + 8 * i];
        float acc[4];
        qk_dot4(k4, qreg, acc);
        if (sub < 4 && grp == 0) sc[sub][nk - 1 - j0] = acc[sub] * scale;
    }
    __syncthreads();

    // ---- phase 2: local softmax stats ----
    if (wid < 4) {
        const int h = wid;
        float m = -1e30f;
        for (int jl = lane; jl < ln; jl += 32) m = fmaxf(m, sc[h][jl]);
        #pragma unroll
        for (int off = 16; off >= 1; off >>= 1)
            m = fmaxf(m, __shfl_xor_sync(0xffffffffu, m, off));
        float s = 0.f;
        for (int jl = lane; jl < ln; jl += 32) {
            float e = __expf(sc[h][jl] - m);
            sc[h][jl] = e;
            s += e;
        }
        #pragma unroll
        for (int off = 16; off >= 1; off >>= 1)
            s += __shfl_xor_sync(0xffffffffu, s, off);
        if (lane == 0) { ssum[h] = s; smax[h] = m; }
    }
    __syncthreads();

    // ---- phase 3: partial O (unnormalized), region-split for MLP ----
    const int half = tid >> 7;
    const int d    = tid & (HD - 1);
    const int mid  = ln >> 1;
    const int La   = j0 + (half ? mid : 0);      // global j range [La, Lb)
    const int Lb   = half ? j1 : (j0 + mid);

    float a[4] = {0.f, 0.f, 0.f, 0.f};

    // segment A: shared prefix
    {
        int sa = La, sb = min(Lb, spl);
        if (sa < sb) {
            const float* p = sh_v + ((size_t)sa * NKV + kvh) * HD + d;
            int jl = sa - j0;
            #pragma unroll 8
            for (int j = sa; j < sb; j++) {
                float v = *p; p += NKV * HD;
                #pragma unroll
                for (int h = 0; h < 4; h++) a[h] = fmaf(sc[h][jl], v, a[h]);
                jl++;
            }
        }
    }
    // segment B: batch cache
    {
        int sa = max(La, spl), sb = min(Lb, nk - 1);
        if (sa < sb) {
            const float* p = cache_v + (((size_t)b * 4096 + (sa - spl)) * NKV + kvh) * HD + d;
            int jl = sa - j0;
            #pragma unroll 8
            for (int j = sa; j < sb; j++) {
                float v = *p; p += NKV * HD;
                #pragma unroll
                for (int h = 0; h < 4; h++) a[h] = fmaf(sc[h][jl], v, a[h]);
                jl++;
            }
        }
    }
    // segment C: the new key (only the half whose range ends at nk)
    if (Lb == nk) {
        float v = g_vnew[((size_t)b * NKV + kvh) * HD + d];
        int jl = (nk - 1) - j0;
        #pragma unroll
        for (int h = 0; h < 4; h++) a[h] = fmaf(sc[h][jl], v, a[h]);
    }

    #pragma unroll
    for (int h = 0; h < 4; h++) sacc[half][h][d] = a[h];
    __syncthreads();

    if (tid < HD) {
        #pragma unroll
        for (int h = 0; h < 4; h++)
            g_pO[((size_t)blk * 4 + h) * HD + tid] = sacc[0][h][tid] + sacc[1][h][tid];
    }
    if (tid < 4) {
        g_pm[((size_t)bk * 4 + tid) * ASPLIT + sp_i] = smax[tid];
        g_ps[((size_t)bk * 4 + tid) * ASPLIT + sp_i] = ssum[tid];
    }
}

// ---------------------------------------------------------------------------------
// Combine attention splits. Grid: BATCH*NKV = 128 blocks, 512 threads (R10 form).
// ---------------------------------------------------------------------------------
__global__ void __launch_bounds__(512) attn_combine()
{
    const int bk  = blockIdx.x;      // b*8 + kvh
    const int tid = threadIdx.x;
    const int h   = tid >> 7;
    const int d   = tid & (HD - 1);
    const int b   = bk >> 3;
    const int kvh = bk & 7;

    const float4* pm4 = (const float4*)&g_pm[((size_t)bk * 4 + h) * ASPLIT];
    const float4* ps4 = (const float4*)&g_ps[((size_t)bk * 4 + h) * ASPLIT];

    float m[ASPLIT], s[ASPLIT];
    #pragma unroll
    for (int q = 0; q < ASPLIT / 4; q++) {
        float4 t = pm4[q];
        m[4*q] = t.x; m[4*q+1] = t.y; m[4*q+2] = t.z; m[4*q+3] = t.w;
        float4 u = ps4[q];
        s[4*q] = u.x; s[4*q+1] = u.y; s[4*q+2] = u.z; s[4*q+3] = u.w;
    }
    float mg = -1e30f;
    #pragma unroll
    for (int i = 0; i < ASPLIT; i++) mg = fmaxf(mg, m[i]);

    float num = 0.f, den = 0.f;
    #pragma unroll
    for (int i = 0; i < ASPLIT; i++) {
        float w = __expf(m[i] - mg);
        num = fmaf(w, g_pO[(((size_t)(bk * ASPLIT + i)) * 4 + h) * HD + d], num);
        den = fmaf(w, s[i], den);
    }
    g_attn[(size_t)b * DMODEL + (size_t)(kvh * 4 + h) * HD + d] = num / den;
}

// ---------------------------------------------------------------------------------
// Final reduce of WO split-K partials into d_out. 65536 elements.
// ---------------------------------------------------------------------------------
__global__ void __launch_bounds__(256) reduce_out(float* __restrict__ out)
{
    int idx = blockIdx.x * 256 + threadIdx.x;    // 0..65535
    int b = idx >> 12;
    int n = idx & 4095;
    float s = 0.f;
    #pragma unroll
    for (int sp = 0; sp < KSPLIT; sp++)
        s += g_part2[(size_t)(sp * 16 + b) * DMODEL + n];
    out[idx] = s;
}

// ---------------------------------------------------------------------------------
extern "C" void kernel_launch(void* const* d_in, const int* in_sizes, int n_in,
                              void* d_out, int out_size)
{
    const float* x        = (const float*)d_in[0];
    const float* wq       = (const float*)d_in[1];
    const float* wk       = (const float*)d_in[2];
    const float* wv       = (const float*)d_in[3];
    const float* wo       = (const float*)d_in[4];
    const float* cache_k  = (const float*)d_in[5];
    const float* cache_v  = (const float*)d_in[6];
    const float* sh_k     = (const float*)d_in[7];
    const float* sh_v     = (const float*)d_in[8];
    const float* fcos     = (const float*)d_in[9];
    const float* fsin     = (const float*)d_in[10];
    const int*   p_sp     = (const int*)d_in[11];
    const int*   p_spl    = (const int*)d_in[12];
    float*       out      = (float*)d_out;

    // 1) QKV projection split-K partials (768 blocks)
    dim3 g1(NQKV / 512, KSPLIT);
    gemm16_part<<<g1, 256>>>(x, wq, wk, wv,
                             4096, 1024, 1024, 4096, 5120, NQKV, 0);

    // 2) reduce + RoPE
    rope_reduce<<<(BATCH * 3072) / 256, 256>>>(fcos, fsin);

    // 3) attention split-KV partials (2048 blocks) + combine
    attn_part<<<BATCH * NKV * ASPLIT, 256>>>(cache_k, cache_v, sh_k, sh_v, p_sp, p_spl);
    attn_combine<<<BATCH * NKV, 512>>>();

    // 4) output projection split-K partials (512 blocks)
    dim3 g2(DMODEL / 512, KSPLIT);
    gemm16_part<<<g2, 256>>>(x, wo, wo, wo,
                             4096, 4096, 4096, 1 << 28, 1 << 29, DMODEL, 1);

    // 5) final reduce into d_out
    reduce_out<<<(BATCH * DMODEL) / 256, 256>>>(out);
}